// round 1
// baseline (speedup 1.0000x reference)
#include <cuda_runtime.h>
#include <cuda_bf16.h>

#define HID 128
#define NNODES 100000
#define NEDGES 1000000

// Scratch: node projections P[node][0:128] = x@W1[0:128], P[node][128:256] = x@W1[128:256]
__device__ float g_P[(size_t)NNODES * 256];

// ----------------------------------------------------------------------------
// Kernel 1: node projection GEMM.  P[i][j] = sum_k x[i][k] * W1row(j)[k][col(j)]
//   j <  128: W1 rows 0..127,  col j
//   j >= 128: W1 rows 128..255, col j-128
// BM=128, BN=64, BK=16, 256 threads, per-thread microtile 8x4.
// ----------------------------------------------------------------------------
__global__ void __launch_bounds__(256) node_proj_kernel(
    const float* __restrict__ x, const float* __restrict__ W1, int n_nodes)
{
    __shared__ float As[16][128];   // [k][m]  (transposed A tile)
    __shared__ float Bs[16][64];    // [k][n]

    const int bm = blockIdx.x * 128;
    const int bn = blockIdx.y * 64;
    // A 64-wide N-tile lies entirely in one half (64 divides 128)
    const float* Wbase = W1 + (bn < 128 ? 0 : 128 * HID);
    const int jc0 = bn & 127;

    const int tid = threadIdx.x;
    const int tx = tid & 15;    // col group: cols tx*4 .. tx*4+3
    const int ty = tid >> 4;    // row group: rows ty*8 .. ty*8+7

    float acc[8][4];
#pragma unroll
    for (int i = 0; i < 8; i++)
#pragma unroll
        for (int j = 0; j < 4; j++) acc[i][j] = 0.f;

    for (int k0 = 0; k0 < HID; k0 += 16) {
        // Load A tile: 128 rows x 16 cols = 512 float4, 2 per thread, store transposed
#pragma unroll
        for (int l = 0; l < 2; l++) {
            int idx = tid + l * 256;      // 0..511
            int r   = idx >> 2;           // 0..127
            int c4  = (idx & 3) * 4;      // 0,4,8,12
            int grow = bm + r;
            float4 v = make_float4(0.f, 0.f, 0.f, 0.f);
            if (grow < n_nodes)
                v = *(const float4*)(x + (size_t)grow * HID + k0 + c4);
            As[c4 + 0][r] = v.x;
            As[c4 + 1][r] = v.y;
            As[c4 + 2][r] = v.z;
            As[c4 + 3][r] = v.w;
        }
        // Load B tile: 16 rows x 64 cols = 256 float4, 1 per thread
        {
            int r  = tid >> 4;            // 0..15
            int c4 = (tid & 15) * 4;      // 0..60
            float4 v = *(const float4*)(Wbase + (size_t)(k0 + r) * HID + jc0 + c4);
            *(float4*)(&Bs[r][c4]) = v;
        }
        __syncthreads();

#pragma unroll
        for (int kk = 0; kk < 16; kk++) {
            float a[8], b[4];
#pragma unroll
            for (int i = 0; i < 8; i++) a[i] = As[kk][ty * 8 + i];
#pragma unroll
            for (int j = 0; j < 4; j++) b[j] = Bs[kk][tx * 4 + j];
#pragma unroll
            for (int i = 0; i < 8; i++)
#pragma unroll
                for (int j = 0; j < 4; j++)
                    acc[i][j] = fmaf(a[i], b[j], acc[i][j]);
        }
        __syncthreads();
    }

#pragma unroll
    for (int i = 0; i < 8; i++) {
        int grow = bm + ty * 8 + i;
        if (grow < n_nodes) {
            float4 v = make_float4(acc[i][0], acc[i][1], acc[i][2], acc[i][3]);
            *(float4*)(g_P + (size_t)grow * 256 + bn + tx * 4) = v;
        }
    }
}

// ----------------------------------------------------------------------------
// Kernel 2: per-edge MLP tail.
// One warp processes 4 edges per iteration (shares W2 column reads 4-ways).
//   h  = relu(P_a[src] + P_b[dst] + ea*w1c + b1)     [128]
//   h2 = relu(h @ W2 + b2)                            [32]  (lane j -> col j)
//   out = sigmoid(sum_j h2[j]*W3[j] + b3)
// ----------------------------------------------------------------------------
#define EDGES_PER_WARP 4
#define WARPS_PER_BLOCK 8

__global__ void __launch_bounds__(256) edge_mlp_kernel(
    const int*   __restrict__ edge_index,   // [2*E]: src then dst
    const float* __restrict__ eattr,        // [E]
    const float* __restrict__ W1,           // [257*128], row 256 = w1c
    const float* __restrict__ b1,           // [128]
    const float* __restrict__ W2,           // [128*32]
    const float* __restrict__ b2,           // [32]
    const float* __restrict__ W3,           // [32]
    const float* __restrict__ b3,           // [1]
    float*       __restrict__ out,          // [E]
    int n_edges)
{
    __shared__ float sW2T[32][132];   // W2 transposed + padded (conflict-free LDS.128)
    __shared__ float sW3[32];
    __shared__ float sb2[32];
    __shared__ float hbuf[WARPS_PER_BLOCK][EDGES_PER_WARP][128];

    const int tid = threadIdx.x;
    // W2 row-major [128][32]: element i = W2[k*32+j] -> sW2T[j][k]
    for (int i = tid; i < 128 * 32; i += 256) {
        int k = i >> 5, j = i & 31;
        sW2T[j][k] = W2[i];
    }
    if (tid < 32) { sW3[tid] = W3[tid]; sb2[tid] = b2[tid]; }
    __syncthreads();

    const int warp = tid >> 5;
    const int lane = tid & 31;

    // Hoisted per-lane constants
    const float4 wc  = *((const float4*)(W1 + 256 * HID) + lane);
    const float4 bb1 = *((const float4*)b1 + lane);
    const float  b3v = b3[0];

    const int gw = blockIdx.x * WARPS_PER_BLOCK + warp;       // global warp id
    const int nwarps = gridDim.x * WARPS_PER_BLOCK;
    const int* __restrict__ src = edge_index;
    const int* __restrict__ dst = edge_index + n_edges;

    for (int base = gw * EDGES_PER_WARP; base < n_edges; base += nwarps * EDGES_PER_WARP) {
        const int cnt = min(EDGES_PER_WARP, n_edges - base);

        // ---- layer 1: gather + add + relu, stash h in shared ----
#pragma unroll
        for (int i = 0; i < EDGES_PER_WARP; i++) {
            if (i < cnt) {
                int e = base + i;
                int s = src[e];
                int d = dst[e];
                float ea = eattr[e];
                float4 va = *((const float4*)(g_P + (size_t)s * 256) + lane);
                float4 vb = *((const float4*)(g_P + (size_t)d * 256 + 128) + lane);
                float4 h;
                h.x = fmaxf(fmaf(ea, wc.x, va.x + vb.x) + bb1.x, 0.f);
                h.y = fmaxf(fmaf(ea, wc.y, va.y + vb.y) + bb1.y, 0.f);
                h.z = fmaxf(fmaf(ea, wc.z, va.z + vb.z) + bb1.z, 0.f);
                h.w = fmaxf(fmaf(ea, wc.w, va.w + vb.w) + bb1.w, 0.f);
                *(float4*)(&hbuf[warp][i][lane * 4]) = h;
            }
        }
        __syncwarp();

        // ---- layer 2: lane j computes col j for all 4 edges (shared W2 reads) ----
        float acc0 = sb2[lane], acc1 = sb2[lane], acc2 = sb2[lane], acc3 = sb2[lane];
#pragma unroll
        for (int k4 = 0; k4 < 128; k4 += 4) {
            float4 wv = *(const float4*)(&sW2T[lane][k4]);
            float4 h0 = *(const float4*)(&hbuf[warp][0][k4]);
            float4 h1 = *(const float4*)(&hbuf[warp][1][k4]);
            float4 h2 = *(const float4*)(&hbuf[warp][2][k4]);
            float4 h3 = *(const float4*)(&hbuf[warp][3][k4]);
            acc0 = fmaf(h0.x, wv.x, acc0); acc0 = fmaf(h0.y, wv.y, acc0);
            acc0 = fmaf(h0.z, wv.z, acc0); acc0 = fmaf(h0.w, wv.w, acc0);
            acc1 = fmaf(h1.x, wv.x, acc1); acc1 = fmaf(h1.y, wv.y, acc1);
            acc1 = fmaf(h1.z, wv.z, acc1); acc1 = fmaf(h1.w, wv.w, acc1);
            acc2 = fmaf(h2.x, wv.x, acc2); acc2 = fmaf(h2.y, wv.y, acc2);
            acc2 = fmaf(h2.z, wv.z, acc2); acc2 = fmaf(h2.w, wv.w, acc2);
            acc3 = fmaf(h3.x, wv.x, acc3); acc3 = fmaf(h3.y, wv.y, acc3);
            acc3 = fmaf(h3.z, wv.z, acc3); acc3 = fmaf(h3.w, wv.w, acc3);
        }

        // ---- layer 3 + sigmoid ----
        float accs[EDGES_PER_WARP] = {acc0, acc1, acc2, acc3};
#pragma unroll
        for (int i = 0; i < EDGES_PER_WARP; i++) {
            if (i < cnt) {
                float r = fmaxf(accs[i], 0.f) * sW3[lane];
#pragma unroll
                for (int m = 16; m > 0; m >>= 1)
                    r += __shfl_xor_sync(0xffffffffu, r, m);
                if (lane == 0) {
                    float z = r + b3v;
                    out[base + i] = 1.f / (1.f + __expf(-z));
                }
            }
        }
        __syncwarp();   // protect hbuf before next iteration overwrites it
    }
}

// ----------------------------------------------------------------------------
// Launch
// ----------------------------------------------------------------------------
extern "C" void kernel_launch(void* const* d_in, const int* in_sizes, int n_in,
                              void* d_out, int out_size)
{
    const float* x     = (const float*)d_in[0];
    const int*   ei    = (const int*)d_in[1];
    const float* ea    = (const float*)d_in[2];
    const float* W1    = (const float*)d_in[3];
    const float* b1    = (const float*)d_in[4];
    const float* W2    = (const float*)d_in[5];
    const float* b2    = (const float*)d_in[6];
    const float* W3    = (const float*)d_in[7];
    const float* b3    = (const float*)d_in[8];
    float*       out   = (float*)d_out;

    const int n_nodes = in_sizes[0] / HID;     // 100000
    const int n_edges = in_sizes[2];           // 1000000

    // Kernel 1: node projections
    dim3 g1((n_nodes + 127) / 128, 4);
    node_proj_kernel<<<g1, 256>>>(x, W1, n_nodes);

    // Kernel 2: per-edge MLP (grid-stride over edges)
    const int blocks = 1184;   // ~8 blocks/SM worth; grid-stride handles the rest
    edge_mlp_kernel<<<blocks, 256>>>(ei, ea, W1, b1, W2, b2, W3, b3, out, n_edges);
}

// round 4
// speedup vs baseline: 1.8398x; 1.8398x over previous
#include <cuda_runtime.h>
#include <cuda_bf16.h>
#include <cstdint>

#define HID 128
#define NNODES 100000

// Scratch: node projections P[node][0:128] = x@W1[0:128], P[node][128:256] = x@W1[128:256]
__device__ float g_P[(size_t)NNODES * 256];

// ----------------------------------------------------------------------------
// Portable tensor-core helpers (no sm_103a-only features!)
// ----------------------------------------------------------------------------
__device__ __forceinline__ uint32_t f2tf32(float f) {
    uint32_t u;
    asm("cvt.rna.tf32.f32 %0, %1;" : "=r"(u) : "f"(f));
    return u;
}

// D[16x8] += A[16x8] * B[8x8], tf32 inputs, fp32 accum (A row-major, B col-major)
__device__ __forceinline__ void mma_tf32(float* d, const uint32_t* a, uint32_t b0, uint32_t b1) {
    asm volatile(
        "mma.sync.aligned.m16n8k8.row.col.f32.tf32.tf32.f32 "
        "{%0,%1,%2,%3}, {%4,%5,%6,%7}, {%8,%9}, {%0,%1,%2,%3};"
        : "+f"(d[0]), "+f"(d[1]), "+f"(d[2]), "+f"(d[3])
        : "r"(a[0]), "r"(a[1]), "r"(a[2]), "r"(a[3]), "r"(b0), "r"(b1));
}

// ----------------------------------------------------------------------------
// Kernel 1: node projection GEMM (scalar fp32, at scalar roofline ~165us)
// ----------------------------------------------------------------------------
__global__ void __launch_bounds__(256) node_proj_kernel(
    const float* __restrict__ x, const float* __restrict__ W1, int n_nodes)
{
    __shared__ float As[16][128];
    __shared__ float Bs[16][64];

    const int bm = blockIdx.x * 128;
    const int bn = blockIdx.y * 64;
    const float* Wbase = W1 + (bn < 128 ? 0 : 128 * HID);
    const int jc0 = bn & 127;

    const int tid = threadIdx.x;
    const int tx = tid & 15;
    const int ty = tid >> 4;

    float acc[8][4];
#pragma unroll
    for (int i = 0; i < 8; i++)
#pragma unroll
        for (int j = 0; j < 4; j++) acc[i][j] = 0.f;

    for (int k0 = 0; k0 < HID; k0 += 16) {
#pragma unroll
        for (int l = 0; l < 2; l++) {
            int idx = tid + l * 256;
            int r = idx >> 2;
            int c4 = (idx & 3) * 4;
            int grow = bm + r;
            float4 v = make_float4(0.f, 0.f, 0.f, 0.f);
            if (grow < n_nodes)
                v = *(const float4*)(x + (size_t)grow * HID + k0 + c4);
            As[c4 + 0][r] = v.x;
            As[c4 + 1][r] = v.y;
            As[c4 + 2][r] = v.z;
            As[c4 + 3][r] = v.w;
        }
        {
            int r = tid >> 4;
            int c4 = (tid & 15) * 4;
            float4 v = *(const float4*)(Wbase + (size_t)(k0 + r) * HID + jc0 + c4);
            *(float4*)(&Bs[r][c4]) = v;
        }
        __syncthreads();

#pragma unroll
        for (int kk = 0; kk < 16; kk++) {
            float a[8], b[4];
#pragma unroll
            for (int i = 0; i < 8; i++) a[i] = As[kk][ty * 8 + i];
#pragma unroll
            for (int j = 0; j < 4; j++) b[j] = Bs[kk][tx * 4 + j];
#pragma unroll
            for (int i = 0; i < 8; i++)
#pragma unroll
                for (int j = 0; j < 4; j++)
                    acc[i][j] = fmaf(a[i], b[j], acc[i][j]);
        }
        __syncthreads();
    }

#pragma unroll
    for (int i = 0; i < 8; i++) {
        int grow = bm + ty * 8 + i;
        if (grow < n_nodes) {
            float4 v = make_float4(acc[i][0], acc[i][1], acc[i][2], acc[i][3]);
            *(float4*)(g_P + (size_t)grow * 256 + bn + tx * 4) = v;
        }
    }
}

// ----------------------------------------------------------------------------
// Kernel 2: edge MLP. Each warp processes independent 16-edge tiles.
//  layer 1: gather P[src]+P[dst]+ea*wc+b1, relu -> tf32 smem buffer [16][132]
//  layer 2: mma.sync tf32: [16,128]@[128,32] via 16 K-chunks x 4 N-tiles
//  layer 3: +b2, relu, *W3 (per-lane regs), quad shfl reduce, sigmoid, store
// ----------------------------------------------------------------------------
#define EWARPS 4           // warps per block
#define ETHREADS (EWARPS * 32)
#define HPAD 132           // padded row stride (floats): bank-conflict-free
#define HBUF_FLOATS (16 * HPAD)
#define W2F_U2 (16 * 4 * 32)                 // 2048 uint2 = 16KB
#define SMEM_EDGE_BYTES (W2F_U2 * 8 + EWARPS * HBUF_FLOATS * 4)

__global__ void __launch_bounds__(ETHREADS) edge_mlp_kernel(
    const int*   __restrict__ edge_index,   // [2*E]: src then dst
    const float* __restrict__ eattr,        // [E]
    const float* __restrict__ W1,           // [257*128], row 256 = w1c
    const float* __restrict__ b1,           // [128]
    const float* __restrict__ W2,           // [128*32]
    const float* __restrict__ b2,           // [32]
    const float* __restrict__ W3,           // [32]
    const float* __restrict__ b3,           // [1]
    float*       __restrict__ out,          // [E]
    int n_edges)
{
    extern __shared__ char smem[];
    uint2* __restrict__ w2f  = (uint2*)smem;                        // fragment-packed W2 (tf32)
    const int tid  = threadIdx.x;
    const int wid  = tid >> 5;
    const int lane = tid & 31;
    uint32_t* __restrict__ hbuf = (uint32_t*)(smem + W2F_U2 * 8) + wid * HBUF_FLOATS;

    // --- pack W2 into mma B-fragment order (tf32), once per block ---
    // frag for (kc, nt): lane holds b0=W2[kc*8+(lane&3)][nt*8+(lane>>2)], b1=+4 row
    for (int i = tid; i < W2F_U2; i += ETHREADS) {
        int kc = i >> 7;
        int nt = (i >> 5) & 3;
        int ln = i & 31;
        int krow = kc * 8 + (ln & 3);
        int col  = nt * 8 + (ln >> 2);
        w2f[i] = make_uint2(f2tf32(W2[krow * 32 + col]),
                            f2tf32(W2[(krow + 4) * 32 + col]));
    }
    __syncthreads();

    // --- per-lane constants ---
    const float4 wc  = ((const float4*)(W1 + 256 * HID))[lane];
    const float4 bb1 = ((const float4*)b1)[lane];
    const float  b3v = b3[0];
    // this lane's 8 output columns (C-fragment layout): col = nt*8 + (lane&3)*2 + i
    float w3v[8], b2v[8];
#pragma unroll
    for (int j = 0; j < 8; j++) {
        int col = (j >> 1) * 8 + (lane & 3) * 2 + (j & 1);
        w3v[j] = W3[col];
        b2v[j] = b2[col];
    }

    const int* __restrict__ src = edge_index;
    const int* __restrict__ dst = edge_index + n_edges;

    const int gw = blockIdx.x * EWARPS + wid;
    const int nwarps = gridDim.x * EWARPS;
    const int ntiles = (n_edges + 15) >> 4;
    const int r0 = lane >> 2;          // C/A fragment row group
    const int tq = lane & 3;           // thread-in-quad

    for (int t = gw; t < ntiles; t += nwarps) {
        const int base = t << 4;

        // ---- stage edge indices (lanes 0..15), broadcast via shfl ----
        int sA = 0, dA = 0;
        float eaA = 0.f;
        if (lane < 16) {
            int e = base + lane;
            if (e < n_edges) { sA = src[e]; dA = dst[e]; eaA = eattr[e]; }
        }

        // ---- layer 1: gather + relu -> tf32 smem tile [16][HPAD] ----
#pragma unroll
        for (int rr = 0; rr < 16; rr++) {
            int   s  = __shfl_sync(0xffffffffu, sA, rr);
            int   dd = __shfl_sync(0xffffffffu, dA, rr);
            float ea = __shfl_sync(0xffffffffu, eaA, rr);
            float4 va = ((const float4*)(g_P + (size_t)s  * 256))[lane];
            float4 vb = ((const float4*)(g_P + (size_t)dd * 256 + 128))[lane];
            uint4 hv;
            hv.x = f2tf32(fmaxf(fmaf(ea, wc.x, va.x + vb.x) + bb1.x, 0.f));
            hv.y = f2tf32(fmaxf(fmaf(ea, wc.y, va.y + vb.y) + bb1.y, 0.f));
            hv.z = f2tf32(fmaxf(fmaf(ea, wc.z, va.z + vb.z) + bb1.z, 0.f));
            hv.w = f2tf32(fmaxf(fmaf(ea, wc.w, va.w + vb.w) + bb1.w, 0.f));
            *(uint4*)(hbuf + rr * HPAD + lane * 4) = hv;
        }
        __syncwarp();

        // ---- layer 2: tf32 mma, D[16][32] ----
        float dacc[4][4];
#pragma unroll
        for (int nt = 0; nt < 4; nt++)
#pragma unroll
            for (int j = 0; j < 4; j++) dacc[nt][j] = 0.f;

#pragma unroll
        for (int kc = 0; kc < 16; kc++) {
            uint32_t a[4];
            const uint32_t* hb = hbuf + kc * 8 + tq;
            a[0] = hb[r0 * HPAD];
            a[1] = hb[(r0 + 8) * HPAD];
            a[2] = hb[r0 * HPAD + 4];
            a[3] = hb[(r0 + 8) * HPAD + 4];
            const uint2* wrow = w2f + kc * 4 * 32 + lane;
#pragma unroll
            for (int nt = 0; nt < 4; nt++) {
                uint2 bv = wrow[nt * 32];
                mma_tf32(dacc[nt], a, bv.x, bv.y);
            }
        }
        __syncwarp();   // all lanes done reading hbuf before next tile overwrites

        // ---- layer 3: +b2, relu, *W3, quad-reduce, sigmoid ----
        float acc0 = 0.f, acc1 = 0.f;   // rows base+r0 and base+r0+8
#pragma unroll
        for (int nt = 0; nt < 4; nt++) {
#pragma unroll
            for (int i = 0; i < 2; i++) {
                int j = nt * 2 + i;
                acc0 = fmaf(fmaxf(dacc[nt][i]     + b2v[j], 0.f), w3v[j], acc0);
                acc1 = fmaf(fmaxf(dacc[nt][2 + i] + b2v[j], 0.f), w3v[j], acc1);
            }
        }
        acc0 += __shfl_xor_sync(0xffffffffu, acc0, 1);
        acc0 += __shfl_xor_sync(0xffffffffu, acc0, 2);
        acc1 += __shfl_xor_sync(0xffffffffu, acc1, 1);
        acc1 += __shfl_xor_sync(0xffffffffu, acc1, 2);
        if (tq == 0) {
            int e0 = base + r0;
            int e1 = base + r0 + 8;
            if (e0 < n_edges) {
                float z = acc0 + b3v;
                out[e0] = 1.f / (1.f + __expf(-z));
            }
            if (e1 < n_edges) {
                float z = acc1 + b3v;
                out[e1] = 1.f / (1.f + __expf(-z));
            }
        }
    }
}

// ----------------------------------------------------------------------------
// Launch
// ----------------------------------------------------------------------------
extern "C" void kernel_launch(void* const* d_in, const int* in_sizes, int n_in,
                              void* d_out, int out_size)
{
    const float* x  = (const float*)d_in[0];
    const int*   ei = (const int*)d_in[1];
    const float* ea = (const float*)d_in[2];
    const float* W1 = (const float*)d_in[3];
    const float* b1 = (const float*)d_in[4];
    const float* W2 = (const float*)d_in[5];
    const float* b2 = (const float*)d_in[6];
    const float* W3 = (const float*)d_in[7];
    const float* b3 = (const float*)d_in[8];
    float*       out = (float*)d_out;

    const int n_nodes = in_sizes[0] / HID;     // 100000
    const int n_edges = in_sizes[2];           // 1000000

    // Kernel 1: node projections
    dim3 g1((n_nodes + 127) / 128, 4);
    node_proj_kernel<<<g1, 256>>>(x, W1, n_nodes);

    // Kernel 2: edge MLP with tf32 mma.sync layer-2
    static int smem_set = 0;
    if (!smem_set) {
        cudaFuncSetAttribute(edge_mlp_kernel,
                             cudaFuncAttributeMaxDynamicSharedMemorySize, SMEM_EDGE_BYTES);
        smem_set = 1;
    }
    const int blocks = 592;   // 4 blocks/SM target; grid-stride over 16-edge tiles
    edge_mlp_kernel<<<blocks, ETHREADS, SMEM_EDGE_BYTES>>>(
        ei, ea, W1, b1, W2, b2, W3, b3, out, n_edges);
}

// round 5
// speedup vs baseline: 2.4125x; 1.3113x over previous
#include <cuda_runtime.h>
#include <cuda_bf16.h>
#include <cstdint>

#define HID 128
#define NNODES 100000

// Scratch: node projections P[node][0:128] = x@W1[0:128], P[node][128:256] = x@W1[128:256]
__device__ float g_P[(size_t)NNODES * 256];

// ----------------------------------------------------------------------------
// Portable tensor-core helpers (mma.sync only — tcgen05 not available on
// this harness's sm_103 PTX target)
// ----------------------------------------------------------------------------
__device__ __forceinline__ uint32_t f2tf32(float f) {
    uint32_t u;
    asm("cvt.rna.tf32.f32 %0, %1;" : "=r"(u) : "f"(f));
    return u;
}

// D[16x8] += A[16x8] * B[8x8], tf32 inputs, fp32 accum (A row-major, B col-major)
__device__ __forceinline__ void mma_tf32(float* d, const uint32_t* a, uint32_t b0, uint32_t b1) {
    asm volatile(
        "mma.sync.aligned.m16n8k8.row.col.f32.tf32.tf32.f32 "
        "{%0,%1,%2,%3}, {%4,%5,%6,%7}, {%8,%9}, {%0,%1,%2,%3};"
        : "+f"(d[0]), "+f"(d[1]), "+f"(d[2]), "+f"(d[3])
        : "r"(a[0]), "r"(a[1]), "r"(a[2]), "r"(a[3]), "r"(b0), "r"(b1));
}

// ----------------------------------------------------------------------------
// Kernel 1: node projection GEMM via tf32 mma.sync.
// P[i][j] = sum_k x[i][k] * W1[(k + (j>=128?128:0))*128 + (j&127)]
// Block tile: M=128 rows x N=128 (one W half). W half resident in smem whole-K
// (Bs[128 n][132 k]); A streamed in K-chunks of 32, double buffered
// (As[2][128][36]). Warp tile 64x32 = 4x4 m16n8k8 fragments.
// ----------------------------------------------------------------------------
#define NP_BS_STRIDE 132
#define NP_AS_STRIDE 36
#define NP_SMEM_BYTES ((128 * NP_BS_STRIDE + 2 * 128 * NP_AS_STRIDE) * 4)

__global__ void __launch_bounds__(256, 2) node_proj_mma_kernel(
    const float* __restrict__ x, const float* __restrict__ W1, int n_nodes)
{
    extern __shared__ uint32_t sm_u[];
    uint32_t* Bs = sm_u;                          // [128 n][132 k] tf32
    uint32_t* As = sm_u + 128 * NP_BS_STRIDE;     // [2][128 m][36 k] tf32

    const int tid  = threadIdx.x;
    const int wid  = tid >> 5;
    const int lane = tid & 31;
    const int g    = lane >> 2;      // fragment row/col group
    const int tq   = lane & 3;       // thread in quad
    const int wm   = wid >> 2;       // 0..1 : warp m index
    const int wn   = wid & 3;        // 0..3 : warp n index

    const int bm  = blockIdx.x * 128;
    const int off = blockIdx.y * 128;   // W1 row offset (which half)

    // ---- load + transpose this W half into Bs[n][k] (once) ----
    for (int i = tid; i < 128 * 32; i += 256) {
        int k  = i >> 5;              // 0..127
        int c4 = (i & 31) * 4;        // n base 0..124
        float4 v = *(const float4*)(W1 + (size_t)(k + off) * HID + c4);
        Bs[(c4 + 0) * NP_BS_STRIDE + k] = f2tf32(v.x);
        Bs[(c4 + 1) * NP_BS_STRIDE + k] = f2tf32(v.y);
        Bs[(c4 + 2) * NP_BS_STRIDE + k] = f2tf32(v.z);
        Bs[(c4 + 3) * NP_BS_STRIDE + k] = f2tf32(v.w);
    }

    // ---- A chunk loader: 128 rows x 32 k ----
    const int a_c4 = (tid & 7) * 4;
    const int a_rb = tid >> 3;
    auto loadA = [&](int buf, int ch) {
        uint32_t* dstp = As + buf * (128 * NP_AS_STRIDE);
#pragma unroll
        for (int p = 0; p < 4; p++) {
            int r = a_rb + p * 32;
            int grow = bm + r;
            float4 v = make_float4(0.f, 0.f, 0.f, 0.f);
            if (grow < n_nodes)
                v = *(const float4*)(x + (size_t)grow * HID + ch * 32 + a_c4);
            uint4 t;
            t.x = f2tf32(v.x); t.y = f2tf32(v.y); t.z = f2tf32(v.z); t.w = f2tf32(v.w);
            *(uint4*)(dstp + r * NP_AS_STRIDE + a_c4) = t;
        }
    };

    loadA(0, 0);
    __syncthreads();

    float acc[4][4][4];
#pragma unroll
    for (int a = 0; a < 4; a++)
#pragma unroll
        for (int b = 0; b < 4; b++)
#pragma unroll
            for (int c = 0; c < 4; c++) acc[a][b][c] = 0.f;

#pragma unroll
    for (int ch = 0; ch < 4; ch++) {
        if (ch < 3) loadA((ch + 1) & 1, ch + 1);   // prefetch into other buffer
        const uint32_t* Ab = As + (ch & 1) * (128 * NP_AS_STRIDE)
                                + (wm * 64 + g) * NP_AS_STRIDE + tq;
        const uint32_t* Bb = Bs + (wn * 32 + g) * NP_BS_STRIDE + ch * 32 + tq;
#pragma unroll
        for (int kc = 0; kc < 4; kc++) {
            uint32_t afr[4][4];
#pragma unroll
            for (int mf = 0; mf < 4; mf++) {
                const uint32_t* ap = Ab + mf * 16 * NP_AS_STRIDE + kc * 8;
                afr[mf][0] = ap[0];
                afr[mf][1] = ap[8 * NP_AS_STRIDE];
                afr[mf][2] = ap[4];
                afr[mf][3] = ap[8 * NP_AS_STRIDE + 4];
            }
            uint32_t bfr[4][2];
#pragma unroll
            for (int nf = 0; nf < 4; nf++) {
                const uint32_t* bp = Bb + nf * 8 * NP_BS_STRIDE + kc * 8;
                bfr[nf][0] = bp[0];
                bfr[nf][1] = bp[4];
            }
#pragma unroll
            for (int mf = 0; mf < 4; mf++)
#pragma unroll
                for (int nf = 0; nf < 4; nf++)
                    mma_tf32(acc[mf][nf], afr[mf], bfr[nf][0], bfr[nf][1]);
        }
        __syncthreads();
    }

    // ---- epilogue: C frag row = mf*16 + g (+8), col = nf*8 + 2tq (+1) ----
#pragma unroll
    for (int mf = 0; mf < 4; mf++) {
        int r0g = bm + wm * 64 + mf * 16 + g;
#pragma unroll
        for (int nf = 0; nf < 4; nf++) {
            int col = off + wn * 32 + nf * 8 + 2 * tq;
            if (r0g < n_nodes)
                *(float2*)(g_P + (size_t)r0g * 256 + col) =
                    make_float2(acc[mf][nf][0], acc[mf][nf][1]);
            if (r0g + 8 < n_nodes)
                *(float2*)(g_P + (size_t)(r0g + 8) * 256 + col) =
                    make_float2(acc[mf][nf][2], acc[mf][nf][3]);
        }
    }
}

// ----------------------------------------------------------------------------
// Kernel 2: edge MLP. 8 warps/block, each warp owns independent 16-edge tiles.
// K-split staging: h computed and MMA'd in two 64-k halves so the per-warp
// staging buffer is 16x68 floats (4.25KB) -> 4 blocks/SM, 32 warps/SM.
// ----------------------------------------------------------------------------
#define EWARPS 8
#define ETHREADS (EWARPS * 32)
#define HSTRIDE 68                     // 64 + 4 pad: frag LDS conflict-free
#define HBUF_WORDS (16 * HSTRIDE)
#define W2F_COUNT (16 * 4 * 32)        // 2048 uint2 = 16KB
#define EDGE_SMEM_BYTES (W2F_COUNT * 8 + EWARPS * HBUF_WORDS * 4)

__device__ __forceinline__ void mma_half(
    float d[4][4], const uint32_t* __restrict__ hbuf,
    const uint2* __restrict__ w2f, int half, int g, int tq, int lane)
{
#pragma unroll
    for (int kc = 0; kc < 8; kc++) {
        const uint32_t* hb = hbuf + kc * 8 + tq;
        uint32_t a[4];
        a[0] = hb[g * HSTRIDE];
        a[1] = hb[(g + 8) * HSTRIDE];
        a[2] = hb[g * HSTRIDE + 4];
        a[3] = hb[(g + 8) * HSTRIDE + 4];
        const uint2* wrow = w2f + (half * 8 + kc) * 128 + lane;
#pragma unroll
        for (int nt = 0; nt < 4; nt++) {
            uint2 bv = wrow[nt * 32];
            mma_tf32(d[nt], a, bv.x, bv.y);
        }
    }
}

__global__ void __launch_bounds__(ETHREADS, 4) edge_mlp_kernel(
    const int*   __restrict__ edge_index,   // [2*E]: src then dst
    const float* __restrict__ eattr,        // [E]
    const float* __restrict__ W1,           // [257*128], row 256 = w1c
    const float* __restrict__ b1,           // [128]
    const float* __restrict__ W2,           // [128*32]
    const float* __restrict__ b2,           // [32]
    const float* __restrict__ W3,           // [32]
    const float* __restrict__ b3,           // [1]
    float*       __restrict__ out,          // [E]
    int n_edges)
{
    extern __shared__ char smem[];
    uint2* __restrict__ w2f = (uint2*)smem;
    const int tid  = threadIdx.x;
    const int wid  = tid >> 5;
    const int lane = tid & 31;
    const int g    = lane >> 2;
    const int tq   = lane & 3;
    uint32_t* __restrict__ hbuf = (uint32_t*)(smem + W2F_COUNT * 8) + wid * HBUF_WORDS;

    // --- pack W2 into mma B-fragment order (tf32), once per block ---
    for (int i = tid; i < W2F_COUNT; i += ETHREADS) {
        int kc = i >> 7;
        int nt = (i >> 5) & 3;
        int ln = i & 31;
        int krow = kc * 8 + (ln & 3);
        int col  = nt * 8 + (ln >> 2);
        w2f[i] = make_uint2(f2tf32(W2[krow * 32 + col]),
                            f2tf32(W2[(krow + 4) * 32 + col]));
    }
    __syncthreads();

    // --- per-lane constants (lane covers h cols {2l,2l+1} and {64+2l,65+2l}) ---
    const float2 wcA = *(const float2*)(W1 + 256 * HID + 2 * lane);
    const float2 wcB = *(const float2*)(W1 + 256 * HID + 64 + 2 * lane);
    const float2 b1A = *(const float2*)(b1 + 2 * lane);
    const float2 b1B = *(const float2*)(b1 + 64 + 2 * lane);
    const float  b3v = b3[0];
    float w3v[8], b2v[8];
#pragma unroll
    for (int j = 0; j < 8; j++) {
        int col = (j >> 1) * 8 + tq * 2 + (j & 1);
        w3v[j] = W3[col];
        b2v[j] = b2[col];
    }

    const int* __restrict__ src = edge_index;
    const int* __restrict__ dst = edge_index + n_edges;

    const int gw = blockIdx.x * EWARPS + wid;
    const int nwarps = gridDim.x * EWARPS;
    const int ntiles = (n_edges + 15) >> 4;

    for (int t = gw; t < ntiles; t += nwarps) {
        const int base = t << 4;

        // ---- stage edge indices (lanes 0..15), broadcast via shfl ----
        int sA = 0, dA = 0;
        float eaA = 0.f;
        if (lane < 16) {
            int e = base + lane;
            if (e < n_edges) { sA = src[e]; dA = dst[e]; eaA = eattr[e]; }
        }

        float dacc[4][4];
#pragma unroll
        for (int nt = 0; nt < 4; nt++)
#pragma unroll
            for (int j = 0; j < 4; j++) dacc[nt][j] = 0.f;

        // ---- half 0: h cols 0..63 ----
#pragma unroll
        for (int rr = 0; rr < 16; rr++) {
            int   s  = __shfl_sync(0xffffffffu, sA, rr);
            int   dd = __shfl_sync(0xffffffffu, dA, rr);
            float ea = __shfl_sync(0xffffffffu, eaA, rr);
            float2 va = *(const float2*)(g_P + (size_t)s  * 256 + 2 * lane);
            float2 vb = *(const float2*)(g_P + (size_t)dd * 256 + 128 + 2 * lane);
            uint2 hv;
            hv.x = f2tf32(fmaxf(fmaf(ea, wcA.x, va.x + vb.x) + b1A.x, 0.f));
            hv.y = f2tf32(fmaxf(fmaf(ea, wcA.y, va.y + vb.y) + b1A.y, 0.f));
            *(uint2*)(hbuf + rr * HSTRIDE + 2 * lane) = hv;
        }
        __syncwarp();
        mma_half(dacc, hbuf, w2f, 0, g, tq, lane);
        __syncwarp();

        // ---- half 1: h cols 64..127 ----
#pragma unroll
        for (int rr = 0; rr < 16; rr++) {
            int   s  = __shfl_sync(0xffffffffu, sA, rr);
            int   dd = __shfl_sync(0xffffffffu, dA, rr);
            float ea = __shfl_sync(0xffffffffu, eaA, rr);
            float2 va = *(const float2*)(g_P + (size_t)s  * 256 + 64 + 2 * lane);
            float2 vb = *(const float2*)(g_P + (size_t)dd * 256 + 192 + 2 * lane);
            uint2 hv;
            hv.x = f2tf32(fmaxf(fmaf(ea, wcB.x, va.x + vb.x) + b1B.x, 0.f));
            hv.y = f2tf32(fmaxf(fmaf(ea, wcB.y, va.y + vb.y) + b1B.y, 0.f));
            *(uint2*)(hbuf + rr * HSTRIDE + 2 * lane) = hv;
        }
        __syncwarp();
        mma_half(dacc, hbuf, w2f, 1, g, tq, lane);
        __syncwarp();   // hbuf safe before next tile overwrites

        // ---- layer 3: +b2, relu, *W3, quad-reduce, sigmoid ----
        float acc0 = 0.f, acc1 = 0.f;   // rows base+g and base+g+8
#pragma unroll
        for (int nt = 0; nt < 4; nt++) {
#pragma unroll
            for (int i = 0; i < 2; i++) {
                int j = nt * 2 + i;
                acc0 = fmaf(fmaxf(dacc[nt][i]     + b2v[j], 0.f), w3v[j], acc0);
                acc1 = fmaf(fmaxf(dacc[nt][2 + i] + b2v[j], 0.f), w3v[j], acc1);
            }
        }
        acc0 += __shfl_xor_sync(0xffffffffu, acc0, 1);
        acc0 += __shfl_xor_sync(0xffffffffu, acc0, 2);
        acc1 += __shfl_xor_sync(0xffffffffu, acc1, 1);
        acc1 += __shfl_xor_sync(0xffffffffu, acc1, 2);
        if (tq == 0) {
            int e0 = base + g;
            int e1 = base + g + 8;
            if (e0 < n_edges) {
                float z = acc0 + b3v;
                out[e0] = 1.f / (1.f + __expf(-z));
            }
            if (e1 < n_edges) {
                float z = acc1 + b3v;
                out[e1] = 1.f / (1.f + __expf(-z));
            }
        }
    }
}

// ----------------------------------------------------------------------------
// Launch
// ----------------------------------------------------------------------------
extern "C" void kernel_launch(void* const* d_in, const int* in_sizes, int n_in,
                              void* d_out, int out_size)
{
    const float* x  = (const float*)d_in[0];
    const int*   ei = (const int*)d_in[1];
    const float* ea = (const float*)d_in[2];
    const float* W1 = (const float*)d_in[3];
    const float* b1 = (const float*)d_in[4];
    const float* W2 = (const float*)d_in[5];
    const float* b2 = (const float*)d_in[6];
    const float* W3 = (const float*)d_in[7];
    const float* b3 = (const float*)d_in[8];
    float*       out = (float*)d_out;

    const int n_nodes = in_sizes[0] / HID;     // 100000
    const int n_edges = in_sizes[2];           // 1000000

    static int smem_set = 0;
    if (!smem_set) {
        cudaFuncSetAttribute(node_proj_mma_kernel,
                             cudaFuncAttributeMaxDynamicSharedMemorySize, NP_SMEM_BYTES);
        cudaFuncSetAttribute(edge_mlp_kernel,
                             cudaFuncAttributeMaxDynamicSharedMemorySize, EDGE_SMEM_BYTES);
        smem_set = 1;
    }

    // Kernel 1: node projections via tf32 mma
    dim3 g1((n_nodes + 127) / 128, 2);
    node_proj_mma_kernel<<<g1, 256, NP_SMEM_BYTES>>>(x, W1, n_nodes);

    // Kernel 2: edge MLP (8 warps/block, 4 blocks/SM target)
    const int blocks = 592;
    edge_mlp_kernel<<<blocks, ETHREADS, EDGE_SMEM_BYTES>>>(
        ei, ea, W1, b1, W2, b2, W3, b3, out, n_edges);
}

// round 7
// speedup vs baseline: 3.0709x; 1.2729x over previous
#include <cuda_runtime.h>
#include <cuda_fp16.h>
#include <cstdint>

#define HID 128
#define NNODES 100000

// Node projections, fp16: P[node][0:128] = x@W1[0:128], [128:256] = x@W1[128:256]
__device__ __half g_Ph[(size_t)NNODES * 256];
// W1 packed into tf32 mma B-fragment order: [2 halves][16 kc][16 nf][32 lanes] uint2
__device__ uint2 g_W1f[2 * 16 * 16 * 32];

// ----------------------------------------------------------------------------
// mma helpers (portable: sm_103 PTX target has no tcgen05)
// ----------------------------------------------------------------------------
__device__ __forceinline__ uint32_t f2tf32(float f) {
    uint32_t u;
    asm("cvt.rna.tf32.f32 %0, %1;" : "=r"(u) : "f"(f));
    return u;
}

// tf32: D[16x8] += A[16x8] * B[8x8]
__device__ __forceinline__ void mma_tf32(float* d, const uint32_t* a, uint32_t b0, uint32_t b1) {
    asm volatile(
        "mma.sync.aligned.m16n8k8.row.col.f32.tf32.tf32.f32 "
        "{%0,%1,%2,%3}, {%4,%5,%6,%7}, {%8,%9}, {%0,%1,%2,%3};"
        : "+f"(d[0]), "+f"(d[1]), "+f"(d[2]), "+f"(d[3])
        : "r"(a[0]), "r"(a[1]), "r"(a[2]), "r"(a[3]), "r"(b0), "r"(b1));
}

// fp16: D[16x8] += A[16x16] * B[16x8], fp32 accum
__device__ __forceinline__ void mma_f16(float* d, const uint32_t* a, uint32_t b0, uint32_t b1) {
    asm volatile(
        "mma.sync.aligned.m16n8k16.row.col.f32.f16.f16.f32 "
        "{%0,%1,%2,%3}, {%4,%5,%6,%7}, {%8,%9}, {%0,%1,%2,%3};"
        : "+f"(d[0]), "+f"(d[1]), "+f"(d[2]), "+f"(d[3])
        : "r"(a[0]), "r"(a[1]), "r"(a[2]), "r"(a[3]), "r"(b0), "r"(b1));
}

__device__ __forceinline__ uint32_t h2_as_u32(__half2 h) {
    uint32_t u;
    memcpy(&u, &h, 4);
    return u;
}

// ----------------------------------------------------------------------------
// Kernel 0: pack W1 into tf32 B-fragment order (once; 128KB, stays L2-hot).
// For half o, tile (kc,nf): lane(g,tq) -> b0=W1[o*128+kc*8+tq][nf*8+g],
//                                        b1=W1[o*128+kc*8+tq+4][nf*8+g]
// ----------------------------------------------------------------------------
__global__ void pack_w1_kernel(const float* __restrict__ W1)
{
    int i = blockIdx.x * blockDim.x + threadIdx.x;
    if (i >= 2 * 16 * 16 * 32) return;
    int o  = i >> 13;
    int kc = (i >> 9) & 15;
    int nf = (i >> 5) & 15;
    int ln = i & 31;
    int g  = ln >> 2, tq = ln & 3;
    int n  = nf * 8 + g;
    int k  = o * 128 + kc * 8 + tq;
    g_W1f[i] = make_uint2(f2tf32(W1[(size_t)k * HID + n]),
                          f2tf32(W1[(size_t)(k + 4) * HID + n]));
}

// ----------------------------------------------------------------------------
// Kernel 1: node projection via tf32 mma; B-frags LDG'd from g_W1f (L2-hot).
// Block tile M=128 x N=128 (one half). A streamed in K-chunks of 32, double
// buffered. Warp tile 64x32 = 4x4 m16n8k8 frags. Output written as fp16.
// ----------------------------------------------------------------------------
#define NP_AS_STRIDE 36
#define NP_SMEM_BYTES (2 * 128 * NP_AS_STRIDE * 4)

__global__ void __launch_bounds__(256, 3) node_proj_mma_kernel(
    const float* __restrict__ x, int n_nodes)
{
    extern __shared__ uint32_t As[];               // [2][128 m][36 k] tf32

    const int tid  = threadIdx.x;
    const int wid  = tid >> 5;
    const int lane = tid & 31;
    const int g    = lane >> 2;
    const int tq   = lane & 3;
    const int wm   = wid >> 2;       // 0..1
    const int wn   = wid & 3;        // 0..3

    const int bm = blockIdx.x * 128;
    const int o  = blockIdx.y;       // which W half / P half

    const int a_c4 = (tid & 7) * 4;
    const int a_rb = tid >> 3;
    auto loadA = [&](int buf, int ch) {
        uint32_t* dstp = As + buf * (128 * NP_AS_STRIDE);
#pragma unroll
        for (int p = 0; p < 4; p++) {
            int r = a_rb + p * 32;
            int grow = bm + r;
            float4 v = make_float4(0.f, 0.f, 0.f, 0.f);
            if (grow < n_nodes)
                v = *(const float4*)(x + (size_t)grow * HID + ch * 32 + a_c4);
            uint4 t;
            t.x = f2tf32(v.x); t.y = f2tf32(v.y); t.z = f2tf32(v.z); t.w = f2tf32(v.w);
            *(uint4*)(dstp + r * NP_AS_STRIDE + a_c4) = t;
        }
    };

    loadA(0, 0);
    __syncthreads();

    float acc[4][4][4];
#pragma unroll
    for (int a = 0; a < 4; a++)
#pragma unroll
        for (int b = 0; b < 4; b++)
#pragma unroll
            for (int c = 0; c < 4; c++) acc[a][b][c] = 0.f;

    const uint2* __restrict__ wf_base = g_W1f + ((size_t)o * 16 * 16 + wn * 4) * 32 + lane;

#pragma unroll
    for (int ch = 0; ch < 4; ch++) {
        if (ch < 3) loadA((ch + 1) & 1, ch + 1);
        const uint32_t* Ab = As + (ch & 1) * (128 * NP_AS_STRIDE)
                                + (wm * 64 + g) * NP_AS_STRIDE + tq;
#pragma unroll
        for (int kc = 0; kc < 4; kc++) {
            // B frags for this global k-chunk, 4 n-frags (coalesced LDG, L2-hot)
            uint2 bfr[4];
            const uint2* wf = wf_base + (size_t)(ch * 4 + kc) * 16 * 32;
#pragma unroll
            for (int nf = 0; nf < 4; nf++) bfr[nf] = wf[nf * 32];

            uint32_t afr[4][4];
#pragma unroll
            for (int mf = 0; mf < 4; mf++) {
                const uint32_t* ap = Ab + mf * 16 * NP_AS_STRIDE + kc * 8;
                afr[mf][0] = ap[0];
                afr[mf][1] = ap[8 * NP_AS_STRIDE];
                afr[mf][2] = ap[4];
                afr[mf][3] = ap[8 * NP_AS_STRIDE + 4];
            }
#pragma unroll
            for (int mf = 0; mf < 4; mf++)
#pragma unroll
                for (int nf = 0; nf < 4; nf++)
                    mma_tf32(acc[mf][nf], afr[mf], bfr[nf].x, bfr[nf].y);
        }
        __syncthreads();
    }

    // epilogue: fp16 P. row = bm+wm*64+mf*16+g (+8); col = o*128+wn*32+nf*8+2tq (+1)
#pragma unroll
    for (int mf = 0; mf < 4; mf++) {
        int r0g = bm + wm * 64 + mf * 16 + g;
#pragma unroll
        for (int nf = 0; nf < 4; nf++) {
            int col = o * 128 + wn * 32 + nf * 8 + 2 * tq;
            if (r0g < n_nodes)
                *(__half2*)(g_Ph + (size_t)r0g * 256 + col) =
                    __floats2half2_rn(acc[mf][nf][0], acc[mf][nf][1]);
            if (r0g + 8 < n_nodes)
                *(__half2*)(g_Ph + (size_t)(r0g + 8) * 256 + col) =
                    __floats2half2_rn(acc[mf][nf][2], acc[mf][nf][3]);
        }
    }
}

// ----------------------------------------------------------------------------
// Kernel 2: edge MLP, fp16 layer-2 mma (m16n8k16). 8 warps/block, each warp
// owns independent 16-edge tiles; full K=128 staged at once (fp16 halves size).
// ----------------------------------------------------------------------------
#define EWARPS 8
#define ETHREADS (EWARPS * 32)
#define HS 136                          // halves per hbuf row (68 words; 68%32==4)
#define HBUF_WORDS (16 * (HS / 2))
#define W2F_COUNT (8 * 4 * 32)          // 1024 uint2 = 8KB
// smem: w2f(8KB) + b2(128B) + w3(128B) + 8 * hbuf(4352B)
#define EDGE_SMEM_BYTES (W2F_COUNT * 8 + 256 + EWARPS * HBUF_WORDS * 4)

__global__ void __launch_bounds__(ETHREADS, 4) edge_mlp_kernel(
    const int*   __restrict__ edge_index,   // [2*E]: src then dst
    const float* __restrict__ eattr,        // [E]
    const float* __restrict__ W1,           // [257*128], row 256 = w1c
    const float* __restrict__ b1,           // [128]
    const float* __restrict__ W2,           // [128*32]
    const float* __restrict__ b2,           // [32]
    const float* __restrict__ W3,           // [32]
    const float* __restrict__ b3,           // [1]
    float*       __restrict__ out,          // [E]
    int n_edges)
{
    extern __shared__ char smem[];
    uint2* __restrict__ w2f  = (uint2*)smem;                       // fp16 B frags
    float* __restrict__ s_b2 = (float*)(smem + W2F_COUNT * 8);     // [32]
    float* __restrict__ s_w3 = s_b2 + 32;                          // [32]
    uint32_t* __restrict__ hb_all = (uint32_t*)(smem + W2F_COUNT * 8 + 256);

    const int tid  = threadIdx.x;
    const int wid  = tid >> 5;
    const int lane = tid & 31;
    const int g    = lane >> 2;
    const int tq   = lane & 3;
    uint32_t* __restrict__ hbuf = hb_all + wid * HBUF_WORDS;

    // --- pack W2 into fp16 m16n8k16 B-fragment order ---
    // tile(kc k16, nt n8): lane(g,tq): b0 = W2[kc*16+2tq +0/1][nt*8+g] pair,
    //                                  b1 = W2[kc*16+2tq+8+0/1][nt*8+g] pair
    for (int i = tid; i < W2F_COUNT; i += ETHREADS) {
        int kc = i >> 7;
        int nt = (i >> 5) & 3;
        int ln = i & 31;
        int col = nt * 8 + (ln >> 2);
        int k0  = kc * 16 + (ln & 3) * 2;
        __half2 lo = __floats2half2_rn(W2[k0 * 32 + col],       W2[(k0 + 1) * 32 + col]);
        __half2 hi = __floats2half2_rn(W2[(k0 + 8) * 32 + col], W2[(k0 + 9) * 32 + col]);
        w2f[i] = make_uint2(h2_as_u32(lo), h2_as_u32(hi));
    }
    if (tid < 32) { s_b2[tid] = b2[tid]; s_w3[tid] = W3[tid]; }
    __syncthreads();

    // --- per-lane layer-1 constants: lane covers h cols 4l..4l+3 ---
    const float4 wc  = ((const float4*)(W1 + 256 * HID))[lane];
    const float4 bb1 = ((const float4*)b1)[lane];
    const float  b3v = b3[0];

    const int* __restrict__ src = edge_index;
    const int* __restrict__ dst = edge_index + n_edges;

    const int gw = blockIdx.x * EWARPS + wid;
    const int nwarps = gridDim.x * EWARPS;
    const int ntiles = (n_edges + 15) >> 4;

    for (int t = gw; t < ntiles; t += nwarps) {
        const int base = t << 4;

        // ---- stage edge data (lanes 0..15), broadcast via shfl ----
        int sA = 0, dA = 0;
        float eaA = 0.f;
        if (lane < 16) {
            int e = base + lane;
            if (e < n_edges) { sA = src[e]; dA = dst[e]; eaA = eattr[e]; }
        }

        // ---- layer 1: fp16 gather + relu -> fp16 smem tile [16][HS] ----
#pragma unroll
        for (int rr = 0; rr < 16; rr++) {
            int   s  = __shfl_sync(0xffffffffu, sA, rr);
            int   dd = __shfl_sync(0xffffffffu, dA, rr);
            float ea = __shfl_sync(0xffffffffu, eaA, rr);
            uint2 ua = *((const uint2*)(g_Ph + (size_t)s  * 256) + lane);
            uint2 ub = *((const uint2*)(g_Ph + (size_t)dd * 256 + 128) + lane);
            float2 a01 = __half22float2(*(__half2*)&ua.x);
            float2 a23 = __half22float2(*(__half2*)&ua.y);
            float2 c01 = __half22float2(*(__half2*)&ub.x);
            float2 c23 = __half22float2(*(__half2*)&ub.y);
            float h0 = fmaxf(fmaf(ea, wc.x, a01.x + c01.x) + bb1.x, 0.f);
            float h1 = fmaxf(fmaf(ea, wc.y, a01.y + c01.y) + bb1.y, 0.f);
            float h2 = fmaxf(fmaf(ea, wc.z, a23.x + c23.x) + bb1.z, 0.f);
            float h3 = fmaxf(fmaf(ea, wc.w, a23.y + c23.y) + bb1.w, 0.f);
            __half2 p0 = __floats2half2_rn(h0, h1);
            __half2 p1 = __floats2half2_rn(h2, h3);
            *((uint2*)(hbuf + rr * (HS / 2)) + lane) =
                make_uint2(h2_as_u32(p0), h2_as_u32(p1));
        }
        __syncwarp();

        // ---- layer 2: fp16 mma, D[16][32], 8 k-chunks of 16 ----
        float dacc[4][4];
#pragma unroll
        for (int nt = 0; nt < 4; nt++)
#pragma unroll
            for (int j = 0; j < 4; j++) dacc[nt][j] = 0.f;

#pragma unroll
        for (int kc = 0; kc < 8; kc++) {
            const uint32_t* ap = hbuf + g * (HS / 2) + kc * 8 + tq;
            uint32_t a[4];
            a[0] = ap[0];
            a[1] = ap[8 * (HS / 2)];
            a[2] = ap[4];
            a[3] = ap[8 * (HS / 2) + 4];
            const uint2* wrow = w2f + kc * 128 + lane;
#pragma unroll
            for (int nt = 0; nt < 4; nt++) {
                uint2 bv = wrow[nt * 32];
                mma_f16(dacc[nt], a, bv.x, bv.y);
            }
        }
        __syncwarp();   // hbuf safe before next tile overwrites

        // ---- layer 3: +b2, relu, *W3, quad-reduce, sigmoid ----
        float acc0 = 0.f, acc1 = 0.f;   // rows base+g and base+g+8
#pragma unroll
        for (int nt = 0; nt < 4; nt++) {
#pragma unroll
            for (int i = 0; i < 2; i++) {
                int col = nt * 8 + 2 * tq + i;
                float w3c = s_w3[col], b2c = s_b2[col];
                acc0 = fmaf(fmaxf(dacc[nt][i]     + b2c, 0.f), w3c, acc0);
                acc1 = fmaf(fmaxf(dacc[nt][2 + i] + b2c, 0.f), w3c, acc1);
            }
        }
        acc0 += __shfl_xor_sync(0xffffffffu, acc0, 1);
        acc0 += __shfl_xor_sync(0xffffffffu, acc0, 2);
        acc1 += __shfl_xor_sync(0xffffffffu, acc1, 1);
        acc1 += __shfl_xor_sync(0xffffffffu, acc1, 2);
        if (tq == 0) {
            int e0 = base + g;
            int e1 = base + g + 8;
            if (e0 < n_edges) {
                float z = acc0 + b3v;
                out[e0] = 1.f / (1.f + __expf(-z));
            }
            if (e1 < n_edges) {
                float z = acc1 + b3v;
                out[e1] = 1.f / (1.f + __expf(-z));
            }
        }
    }
}

// ----------------------------------------------------------------------------
// Launch
// ----------------------------------------------------------------------------
extern "C" void kernel_launch(void* const* d_in, const int* in_sizes, int n_in,
                              void* d_out, int out_size)
{
    const float* x  = (const float*)d_in[0];
    const int*   ei = (const int*)d_in[1];
    const float* ea = (const float*)d_in[2];
    const float* W1 = (const float*)d_in[3];
    const float* b1 = (const float*)d_in[4];
    const float* W2 = (const float*)d_in[5];
    const float* b2 = (const float*)d_in[6];
    const float* W3 = (const float*)d_in[7];
    const float* b3 = (const float*)d_in[8];
    float*       out = (float*)d_out;

    const int n_nodes = in_sizes[0] / HID;     // 100000
    const int n_edges = in_sizes[2];           // 1000000

    static int smem_set = 0;
    if (!smem_set) {
        cudaFuncSetAttribute(node_proj_mma_kernel,
                             cudaFuncAttributeMaxDynamicSharedMemorySize, NP_SMEM_BYTES);
        cudaFuncSetAttribute(edge_mlp_kernel,
                             cudaFuncAttributeMaxDynamicSharedMemorySize, EDGE_SMEM_BYTES);
        smem_set = 1;
    }

    // Kernel 0: pack W1 fragments (L2-hot afterwards)
    pack_w1_kernel<<<64, 256>>>(W1);

    // Kernel 1: node projections (tf32 mma, fp16 output)
    dim3 g1((n_nodes + 127) / 128, 2);
    node_proj_mma_kernel<<<g1, 256, NP_SMEM_BYTES>>>(x, n_nodes);

    // Kernel 2: edge MLP (fp16 mma layer-2)
    const int blocks = 592;
    edge_mlp_kernel<<<blocks, ETHREADS, EDGE_SMEM_BYTES>>>(
        ei, ea, W1, b1, W2, b2, W3, b3, out, n_edges);
}

// round 9
// speedup vs baseline: 4.4962x; 1.4641x over previous
#include <cuda_runtime.h>
#include <cuda_fp16.h>
#include <cstdint>

#define HID 128
#define NNODES 100000

// Node projections, fp16: P[node][0:128] = x@W1[0:128], [128:256] = x@W1[128:256]
__device__ __half g_Ph[(size_t)NNODES * 256];
// W1 packed into fp16 m16n8k16 B-fragment order: [2 halves][8 kc][16 nf][32 lanes] uint2
__device__ uint2 g_W1fh[2 * 8 * 16 * 32];

// ----------------------------------------------------------------------------
// mma helper (portable: sm_103 PTX target has no tcgen05)
// fp16: D[16x8] += A[16x16] * B[16x8], fp32 accum
// ----------------------------------------------------------------------------
__device__ __forceinline__ void mma_f16(float* d, const uint32_t* a, uint32_t b0, uint32_t b1) {
    asm volatile(
        "mma.sync.aligned.m16n8k16.row.col.f32.f16.f16.f32 "
        "{%0,%1,%2,%3}, {%4,%5,%6,%7}, {%8,%9}, {%0,%1,%2,%3};"
        : "+f"(d[0]), "+f"(d[1]), "+f"(d[2]), "+f"(d[3])
        : "r"(a[0]), "r"(a[1]), "r"(a[2]), "r"(a[3]), "r"(b0), "r"(b1));
}

__device__ __forceinline__ uint32_t h2_as_u32(__half2 h) {
    uint32_t u;
    memcpy(&u, &h, 4);
    return u;
}
__device__ __forceinline__ __half2 u32_as_h2(uint32_t u) {
    __half2 h;
    memcpy(&h, &u, 4);
    return h;
}

// ----------------------------------------------------------------------------
// Kernel 0: pack W1 into fp16 m16n8k16 B-fragment order (once; 64KB, L2-hot).
// For half o, tile (kc,nf): lane(g,tq):
//   b0 = {W1[k0][n], W1[k0+1][n]},  b1 = {W1[k0+8][n], W1[k0+9][n]}
//   where k0 = o*128 + kc*16 + 2*tq, n = nf*8 + g
// ----------------------------------------------------------------------------
__global__ void pack_w1_kernel(const float* __restrict__ W1)
{
    int i = blockIdx.x * blockDim.x + threadIdx.x;
    if (i >= 2 * 8 * 16 * 32) return;
    int o  = i >> 12;
    int kc = (i >> 9) & 7;
    int nf = (i >> 5) & 15;
    int ln = i & 31;
    int g  = ln >> 2, tq = ln & 3;
    int n  = nf * 8 + g;
    int k0 = o * 128 + kc * 16 + 2 * tq;
    __half2 b0 = __floats2half2_rn(W1[(size_t)k0 * HID + n],       W1[(size_t)(k0 + 1) * HID + n]);
    __half2 b1 = __floats2half2_rn(W1[(size_t)(k0 + 8) * HID + n], W1[(size_t)(k0 + 9) * HID + n]);
    g_W1fh[i] = make_uint2(h2_as_u32(b0), h2_as_u32(b1));
}

// ----------------------------------------------------------------------------
// Kernel 1: node projection via fp16 mma (m16n8k16); B-frags LDG'd from
// g_W1fh (L2-hot). Block tile M=128 x N=128 (one half). A streamed in
// K-chunks of 32 (fp16), double buffered. Warp tile 64x32 = 4x4 frags.
// A-tile row stride = 20 uint32 (16 half2 + 4 pad) -> conflict-free frag LDS.
// ----------------------------------------------------------------------------
#define NP_AW 20
#define NP_SMEM_BYTES (2 * 128 * NP_AW * 4)

__global__ void __launch_bounds__(256, 3) node_proj_mma_kernel(
    const float* __restrict__ x, int n_nodes)
{
    extern __shared__ uint32_t As[];               // [2][128 m][20 w] fp16x2

    const int tid  = threadIdx.x;
    const int wid  = tid >> 5;
    const int lane = tid & 31;
    const int g    = lane >> 2;
    const int tq   = lane & 3;
    const int wm   = wid >> 2;       // 0..1
    const int wn   = wid & 3;        // 0..3

    const int bm = blockIdx.x * 128;
    const int o  = blockIdx.y;       // which W half / P half

    const int a_k4 = (tid & 7) * 4;  // k offset (halves) within 32-chunk
    const int a_rb = tid >> 3;
    auto loadA = [&](int buf, int ch) {
        uint32_t* dstp = As + buf * (128 * NP_AW);
#pragma unroll
        for (int p = 0; p < 4; p++) {
            int r = a_rb + p * 32;
            int grow = bm + r;
            float4 v = make_float4(0.f, 0.f, 0.f, 0.f);
            if (grow < n_nodes)
                v = *(const float4*)(x + (size_t)grow * HID + ch * 32 + a_k4);
            __half2 p0 = __floats2half2_rn(v.x, v.y);
            __half2 p1 = __floats2half2_rn(v.z, v.w);
            *(uint2*)(dstp + r * NP_AW + (a_k4 >> 1)) =
                make_uint2(h2_as_u32(p0), h2_as_u32(p1));
        }
    };

    loadA(0, 0);
    __syncthreads();

    float acc[4][4][4];
#pragma unroll
    for (int a = 0; a < 4; a++)
#pragma unroll
        for (int b = 0; b < 4; b++)
#pragma unroll
            for (int c = 0; c < 4; c++) acc[a][b][c] = 0.f;

    const uint2* __restrict__ wf_base = g_W1fh + ((size_t)o * 8 * 16 + wn * 4) * 32 + lane;

#pragma unroll
    for (int ch = 0; ch < 4; ch++) {
        if (ch < 3) loadA((ch + 1) & 1, ch + 1);
        const uint32_t* Ab = As + (ch & 1) * (128 * NP_AW)
                                + (wm * 64 + g) * NP_AW + tq;
#pragma unroll
        for (int kk = 0; kk < 2; kk++) {          // two k16 chunks per k32
            // B frags (coalesced LDG, L2-hot)
            uint2 bfr[4];
            const uint2* wf = wf_base + (size_t)(ch * 2 + kk) * 16 * 32;
#pragma unroll
            for (int nf = 0; nf < 4; nf++) bfr[nf] = wf[nf * 32];

            uint32_t afr[4][4];
#pragma unroll
            for (int mf = 0; mf < 4; mf++) {
                const uint32_t* ap = Ab + mf * 16 * NP_AW + kk * 8;
                afr[mf][0] = ap[0];
                afr[mf][1] = ap[8 * NP_AW];
                afr[mf][2] = ap[4];
                afr[mf][3] = ap[8 * NP_AW + 4];
            }
#pragma unroll
            for (int mf = 0; mf < 4; mf++)
#pragma unroll
                for (int nf = 0; nf < 4; nf++)
                    mma_f16(acc[mf][nf], afr[mf], bfr[nf].x, bfr[nf].y);
        }
        __syncthreads();
    }

    // epilogue: fp16 P. row = bm+wm*64+mf*16+g (+8); col = o*128+wn*32+nf*8+2tq (+1)
#pragma unroll
    for (int mf = 0; mf < 4; mf++) {
        int r0g = bm + wm * 64 + mf * 16 + g;
#pragma unroll
        for (int nf = 0; nf < 4; nf++) {
            int col = o * 128 + wn * 32 + nf * 8 + 2 * tq;
            if (r0g < n_nodes)
                *(__half2*)(g_Ph + (size_t)r0g * 256 + col) =
                    __floats2half2_rn(acc[mf][nf][0], acc[mf][nf][1]);
            if (r0g + 8 < n_nodes)
                *(__half2*)(g_Ph + (size_t)(r0g + 8) * 256 + col) =
                    __floats2half2_rn(acc[mf][nf][2], acc[mf][nf][3]);
        }
    }
}

// ----------------------------------------------------------------------------
// Kernel 2: edge MLP, fp16 layer-2 mma (m16n8k16). 8 warps/block, each warp
// owns independent 16-edge tiles. Layer-1 gather arithmetic in half2
// (HADD2/HFMA2/HMAX2) — no fp32 unpack/repack.
// ----------------------------------------------------------------------------
#define EWARPS 8
#define ETHREADS (EWARPS * 32)
#define HS 136                          // halves per hbuf row (68 words; 68%32==4)
#define HBUF_WORDS (16 * (HS / 2))
#define W2F_COUNT (8 * 4 * 32)          // 1024 uint2 = 8KB
// smem: w2f(8KB) + b2(128B) + w3(128B) + 8 * hbuf(4352B)
#define EDGE_SMEM_BYTES (W2F_COUNT * 8 + 256 + EWARPS * HBUF_WORDS * 4)

__global__ void __launch_bounds__(ETHREADS, 4) edge_mlp_kernel(
    const int*   __restrict__ edge_index,   // [2*E]: src then dst
    const float* __restrict__ eattr,        // [E]
    const float* __restrict__ W1,           // [257*128], row 256 = w1c
    const float* __restrict__ b1,           // [128]
    const float* __restrict__ W2,           // [128*32]
    const float* __restrict__ b2,           // [32]
    const float* __restrict__ W3,           // [32]
    const float* __restrict__ b3,           // [1]
    float*       __restrict__ out,          // [E]
    int n_edges)
{
    extern __shared__ char smem[];
    uint2* __restrict__ w2f  = (uint2*)smem;                       // fp16 B frags
    float* __restrict__ s_b2 = (float*)(smem + W2F_COUNT * 8);     // [32]
    float* __restrict__ s_w3 = s_b2 + 32;                          // [32]
    uint32_t* __restrict__ hb_all = (uint32_t*)(smem + W2F_COUNT * 8 + 256);

    const int tid  = threadIdx.x;
    const int wid  = tid >> 5;
    const int lane = tid & 31;
    const int g    = lane >> 2;
    const int tq   = lane & 3;
    uint32_t* __restrict__ hbuf = hb_all + wid * HBUF_WORDS;

    // --- pack W2 into fp16 m16n8k16 B-fragment order ---
    for (int i = tid; i < W2F_COUNT; i += ETHREADS) {
        int kc = i >> 7;
        int nt = (i >> 5) & 3;
        int ln = i & 31;
        int col = nt * 8 + (ln >> 2);
        int k0  = kc * 16 + (ln & 3) * 2;
        __half2 lo = __floats2half2_rn(W2[k0 * 32 + col],       W2[(k0 + 1) * 32 + col]);
        __half2 hi = __floats2half2_rn(W2[(k0 + 8) * 32 + col], W2[(k0 + 9) * 32 + col]);
        w2f[i] = make_uint2(h2_as_u32(lo), h2_as_u32(hi));
    }
    if (tid < 32) { s_b2[tid] = b2[tid]; s_w3[tid] = W3[tid]; }
    __syncthreads();

    // --- per-lane layer-1 constants as half2 (lane covers h cols 4l..4l+3) ---
    const float4 wcf = ((const float4*)(W1 + 256 * HID))[lane];
    const float4 b1f = ((const float4*)b1)[lane];
    const __half2 wc0 = __floats2half2_rn(wcf.x, wcf.y);
    const __half2 wc1 = __floats2half2_rn(wcf.z, wcf.w);
    const __half2 bb0 = __floats2half2_rn(b1f.x, b1f.y);
    const __half2 bb1v = __floats2half2_rn(b1f.z, b1f.w);
    const __half2 zero2 = __floats2half2_rn(0.f, 0.f);
    const float  b3v = b3[0];

    const int* __restrict__ src = edge_index;
    const int* __restrict__ dst = edge_index + n_edges;

    const int gw = blockIdx.x * EWARPS + wid;
    const int nwarps = gridDim.x * EWARPS;
    const int ntiles = (n_edges + 15) >> 4;

    for (int t = gw; t < ntiles; t += nwarps) {
        const int base = t << 4;

        // ---- stage edge data (lanes 0..15), broadcast via shfl ----
        int sA = 0, dA = 0;
        float eaA = 0.f;
        if (lane < 16) {
            int e = base + lane;
            if (e < n_edges) { sA = src[e]; dA = dst[e]; eaA = eattr[e]; }
        }

        // ---- layer 1: half2 gather + relu -> fp16 smem tile [16][HS] ----
#pragma unroll
        for (int rr = 0; rr < 16; rr++) {
            int   s  = __shfl_sync(0xffffffffu, sA, rr);
            int   dd = __shfl_sync(0xffffffffu, dA, rr);
            float ea = __shfl_sync(0xffffffffu, eaA, rr);
            __half2 ea2 = __float2half2_rn(ea);
            uint2 ua = *((const uint2*)(g_Ph + (size_t)s  * 256) + lane);
            uint2 ub = *((const uint2*)(g_Ph + (size_t)dd * 256 + 128) + lane);
            __half2 h0 = __hadd2(__hadd2(u32_as_h2(ua.x), u32_as_h2(ub.x)), bb0);
            __half2 h1 = __hadd2(__hadd2(u32_as_h2(ua.y), u32_as_h2(ub.y)), bb1v);
            h0 = __hmax2(__hfma2(ea2, wc0, h0), zero2);
            h1 = __hmax2(__hfma2(ea2, wc1, h1), zero2);
            *((uint2*)(hbuf + rr * (HS / 2)) + lane) =
                make_uint2(h2_as_u32(h0), h2_as_u32(h1));
        }
        __syncwarp();

        // ---- layer 2: fp16 mma, D[16][32], 8 k-chunks of 16 ----
        float dacc[4][4];
#pragma unroll
        for (int nt = 0; nt < 4; nt++)
#pragma unroll
            for (int j = 0; j < 4; j++) dacc[nt][j] = 0.f;

#pragma unroll
        for (int kc = 0; kc < 8; kc++) {
            const uint32_t* ap = hbuf + g * (HS / 2) + kc * 8 + tq;
            uint32_t a[4];
            a[0] = ap[0];
            a[1] = ap[8 * (HS / 2)];
            a[2] = ap[4];
            a[3] = ap[8 * (HS / 2) + 4];
            const uint2* wrow = w2f + kc * 128 + lane;
#pragma unroll
            for (int nt = 0; nt < 4; nt++) {
                uint2 bv = wrow[nt * 32];
                mma_f16(dacc[nt], a, bv.x, bv.y);
            }
        }
        __syncwarp();   // hbuf safe before next tile overwrites

        // ---- layer 3: +b2, relu, *W3, quad-reduce, sigmoid ----
        float acc0 = 0.f, acc1 = 0.f;   // rows base+g and base+g+8
#pragma unroll
        for (int nt = 0; nt < 4; nt++) {
#pragma unroll
            for (int i = 0; i < 2; i++) {
                int col = nt * 8 + 2 * tq + i;
                float w3c = s_w3[col], b2c = s_b2[col];
                acc0 = fmaf(fmaxf(dacc[nt][i]     + b2c, 0.f), w3c, acc0);
                acc1 = fmaf(fmaxf(dacc[nt][2 + i] + b2c, 0.f), w3c, acc1);
            }
        }
        acc0 += __shfl_xor_sync(0xffffffffu, acc0, 1);
        acc0 += __shfl_xor_sync(0xffffffffu, acc0, 2);
        acc1 += __shfl_xor_sync(0xffffffffu, acc1, 1);
        acc1 += __shfl_xor_sync(0xffffffffu, acc1, 2);
        if (tq == 0) {
            int e0 = base + g;
            int e1 = base + g + 8;
            if (e0 < n_edges) {
                float z = acc0 + b3v;
                out[e0] = 1.f / (1.f + __expf(-z));
            }
            if (e1 < n_edges) {
                float z = acc1 + b3v;
                out[e1] = 1.f / (1.f + __expf(-z));
            }
        }
    }
}

// ----------------------------------------------------------------------------
// Launch
// ----------------------------------------------------------------------------
extern "C" void kernel_launch(void* const* d_in, const int* in_sizes, int n_in,
                              void* d_out, int out_size)
{
    const float* x  = (const float*)d_in[0];
    const int*   ei = (const int*)d_in[1];
    const float* ea = (const float*)d_in[2];
    const float* W1 = (const float*)d_in[3];
    const float* b1 = (const float*)d_in[4];
    const float* W2 = (const float*)d_in[5];
    const float* b2 = (const float*)d_in[6];
    const float* W3 = (const float*)d_in[7];
    const float* b3 = (const float*)d_in[8];
    float*       out = (float*)d_out;

    const int n_nodes = in_sizes[0] / HID;     // 100000
    const int n_edges = in_sizes[2];           // 1000000

    static int smem_set = 0;
    if (!smem_set) {
        cudaFuncSetAttribute(node_proj_mma_kernel,
                             cudaFuncAttributeMaxDynamicSharedMemorySize, NP_SMEM_BYTES);
        cudaFuncSetAttribute(edge_mlp_kernel,
                             cudaFuncAttributeMaxDynamicSharedMemorySize, EDGE_SMEM_BYTES);
        smem_set = 1;
    }

    // Kernel 0: pack W1 fragments (L2-hot afterwards)
    pack_w1_kernel<<<32, 256>>>(W1);

    // Kernel 1: node projections (fp16 mma, fp16 output)
    dim3 g1((n_nodes + 127) / 128, 2);
    node_proj_mma_kernel<<<g1, 256, NP_SMEM_BYTES>>>(x, n_nodes);

    // Kernel 2: edge MLP (fp16 mma layer-2, half2 layer-1)
    const int blocks = 592;
    edge_mlp_kernel<<<blocks, ETHREADS, EDGE_SMEM_BYTES>>>(
        ei, ea, W1, b1, W2, b2, W3, b3, out, n_edges);
}